// round 2
// baseline (speedup 1.0000x reference)
#include <cuda_runtime.h>
#include <cstdint>

#define Bz 32
#define Sz 2048
#define Hz 512
#define Ez 256
#define NLz 2000
#define Tz 32
#define NCH 16
#define CHS 128
#define L2E 1.4426950408889634f

// ---------------- device scratch ----------------
__device__ float g_ctx[(size_t)Bz * Sz * Hz];      // [b*S+s][h]  128 MB
__device__ float g_zg[768 * Bz];                   // gates operand: rows 0..255 x, 256..767 h
__device__ float g_zinp[Hz * Bz];                  // h_lstm, operand for inp
__device__ float g_zho[1024 * Bz];                 // 0..511 weighted, 512..1023 h_lstm
__device__ float g_zlog[1280 * Bz];                // 0..511 h_t, 512..1023 weighted, 1024..1279 x
__device__ float g_gates[4 * Hz * Bz];             // [r][b]
__device__ float g_cbuf[2][Hz * Bz];               // [h][b]
__device__ float g_inp[Bz * Hz];                   // [b][h]
__device__ float g_cw[Bz * NCH * Hz];
__device__ float g_cm[Bz * NCH];
__device__ float g_cd[Bz * NCH];

// ---------------- math ----------------
__device__ __forceinline__ float ex2f(float x) {
    float y; asm("ex2.approx.f32 %0, %1;" : "=f"(y) : "f"(x)); return y;
}
__device__ __forceinline__ float rcpf(float x) {
    float y; asm("rcp.approx.f32 %0, %1;" : "=f"(y) : "f"(x)); return y;
}
__device__ __forceinline__ float mufu_tanh(float x) {
    float e = ex2f(x * (2.0f * L2E));
    return fmaf(-2.0f, rcpf(e + 1.0f), 1.0f);
}
__device__ __forceinline__ float mufu_sigmoid(float x) {
    return rcpf(1.0f + ex2f(-x * L2E));
}
// FFMA-only reciprocal (magic + 3 Newton), q > 0 normal
__device__ __forceinline__ float rcp_nr(float q) {
    float r = __uint_as_float(0x7EF311C3u - __float_as_uint(q));
    r = r * (2.0f - q * r);
    r = r * (2.0f - q * r);
    r = r * (2.0f - q * r);
    return r;
}
// MUFU-free tanh (Eigen rational, abs err ~1e-4 over clamp range)
__device__ __forceinline__ float tanh_ffma(float x) {
    float cx = fminf(fmaxf(x, -7.99881172f), 7.99881172f);
    float x2 = cx * cx;
    float num = fmaf(x2, -2.76076847742355e-16f, 2.00018790482477e-13f);
    num = fmaf(x2, num, -8.60467152213735e-11f);
    num = fmaf(x2, num, 5.12229709037114e-08f);
    num = fmaf(x2, num, 1.48572235717979e-05f);
    num = fmaf(x2, num, 6.37261928875436e-04f);
    num = fmaf(x2, num, 4.89352455891786e-03f);
    num = cx * num;
    float den = fmaf(x2, 1.19825839466702e-06f, 1.18534705686654e-04f);
    den = fmaf(x2, den, 2.26843463243900e-03f);
    den = fmaf(x2, den, 4.89352518554385e-03f);
    return num * rcp_nr(den);
}

// ---------------- warp-row GEMM helper: 4 rows, lane=batch ----------------
template <int K, int LD>
__device__ __forceinline__ void acc4(const float* __restrict__ W, int r0,
                                     const float* __restrict__ z, int lane,
                                     float acc[4]) {
#pragma unroll 4
    for (int k = 0; k < K; k += 4) {
        float z0 = z[(k + 0) * 32 + lane];
        float z1 = z[(k + 1) * 32 + lane];
        float z2 = z[(k + 2) * 32 + lane];
        float z3 = z[(k + 3) * 32 + lane];
#pragma unroll
        for (int i = 0; i < 4; i++) {
            float4 wv = *(const float4*)(W + (size_t)(r0 + i) * LD + k);
            acc[i] = fmaf(wv.x, z0, acc[i]);
            acc[i] = fmaf(wv.y, z1, acc[i]);
            acc[i] = fmaf(wv.z, z2, acc[i]);
            acc[i] = fmaf(wv.w, z3, acc[i]);
        }
    }
}

// ---------------- ctx GEMM (one-time): g_ctx[m][n] = context[m][:]·Wctx[n][:] + bctx[n] ----------------
__global__ void k_ctx_gemm(const float* __restrict__ A, const float* __restrict__ W,
                           const float* __restrict__ bias) {
    __shared__ float As[8][128];
    __shared__ float Ws[8][128];
    int tid = threadIdx.x;
    int bm = blockIdx.x * 128, bn = blockIdx.y * 128;
    int lr = tid >> 1, lk = (tid & 1) * 4;
    int tm = (tid >> 4) * 8, tn = (tid & 15) * 8;
    float acc[8][8];
#pragma unroll
    for (int i = 0; i < 8; i++)
#pragma unroll
        for (int j = 0; j < 8; j++) acc[i][j] = 0.0f;
    const float* Ap = A + (size_t)(bm + lr) * 512 + lk;
    const float* Wp = W + (size_t)(bn + lr) * 512 + lk;
    for (int k0 = 0; k0 < 512; k0 += 8) {
        float4 a4 = *(const float4*)(Ap + k0);
        float4 w4 = *(const float4*)(Wp + k0);
        As[lk + 0][lr] = a4.x; As[lk + 1][lr] = a4.y;
        As[lk + 2][lr] = a4.z; As[lk + 3][lr] = a4.w;
        Ws[lk + 0][lr] = w4.x; Ws[lk + 1][lr] = w4.y;
        Ws[lk + 2][lr] = w4.z; Ws[lk + 3][lr] = w4.w;
        __syncthreads();
#pragma unroll
        for (int kk = 0; kk < 8; kk++) {
            float4 a0 = *(const float4*)&As[kk][tm];
            float4 a1 = *(const float4*)&As[kk][tm + 4];
            float4 w0 = *(const float4*)&Ws[kk][tn];
            float4 w1 = *(const float4*)&Ws[kk][tn + 4];
            float ar[8] = {a0.x, a0.y, a0.z, a0.w, a1.x, a1.y, a1.z, a1.w};
            float wr[8] = {w0.x, w0.y, w0.z, w0.w, w1.x, w1.y, w1.z, w1.w};
#pragma unroll
            for (int i = 0; i < 8; i++)
#pragma unroll
                for (int j = 0; j < 8; j++) acc[i][j] = fmaf(ar[i], wr[j], acc[i][j]);
        }
        __syncthreads();
    }
#pragma unroll
    for (int i = 0; i < 8; i++) {
        float* o = g_ctx + (size_t)(bm + tm + i) * 512 + bn + tn;
#pragma unroll
        for (int j = 0; j < 8; j++) o[j] = acc[i][j] + bias[bn + tn + j];
    }
}

// ---------------- pre: stage x(0) and h0 into g_zg ----------------
__global__ void k_pre(const float* __restrict__ dec, const float* __restrict__ h0) {
    int idx = blockIdx.x * 256 + threadIdx.x;      // 64*256 = 16384
    int b = idx & 31, h = idx >> 5;
    g_zg[(256 + h) * 32 + b] = h0[b * 512 + h];
    if (idx < 8192) {
        int bb = idx >> 8, k = idx & 255;
        g_zg[k * 32 + bb] = dec[bb * 256 + k];
    }
}

// ---------------- gates: 2048 rows ----------------
__global__ void k_gates(const float* __restrict__ Wih, const float* __restrict__ bih,
                        const float* __restrict__ Whh, const float* __restrict__ bhh) {
    int lane = threadIdx.x & 31, w = threadIdx.x >> 5;
    int r0 = (blockIdx.x * 8 + w) * 4;
    float acc[4] = {0, 0, 0, 0};
    acc4<256, 256>(Wih, r0, g_zg, lane, acc);
    acc4<512, 512>(Whh, r0, g_zg + 256 * 32, lane, acc);
#pragma unroll
    for (int i = 0; i < 4; i++)
        g_gates[(r0 + i) * 32 + lane] = acc[i] + bih[r0 + i] + bhh[r0 + i];
}

// ---------------- LSTM pointwise + staging for next/current step ----------------
__global__ void k_point(const float* __restrict__ c0, const float* __restrict__ dec,
                        const int* __restrict__ lab, const float* __restrict__ lemb, int t) {
    int idx = blockIdx.x * 256 + threadIdx.x;      // 16384
    int b = idx & 31, h = idx >> 5;
    const float* cin = g_cbuf[t & 1];
    float* cout = g_cbuf[(t + 1) & 1];
    float gi = mufu_sigmoid(g_gates[h * 32 + b]);
    float gf = mufu_sigmoid(g_gates[(512 + h) * 32 + b]);
    float gg = mufu_tanh(g_gates[(1024 + h) * 32 + b]);
    float go = mufu_sigmoid(g_gates[(1536 + h) * 32 + b]);
    float c_old = (t == 0) ? c0[b * 512 + h] : cin[h * 32 + b];
    float ct = fmaf(gf, c_old, gi * gg);
    float hl = go * mufu_tanh(ct);
    cout[h * 32 + b] = ct;
    g_zinp[h * 32 + b] = hl;
    g_zho[(512 + h) * 32 + b] = hl;
    if (idx < 8192) {
        int bb = idx >> 8, k = idx & 255;
        // x(t) for logits
        float xv = (t == 0) ? dec[bb * 256 + k]
                            : lemb[(size_t)lab[bb * 32 + (t - 1)] * 256 + k];
        g_zlog[(1024 + k) * 32 + bb] = xv;
        // x(t+1) for next gates
        if (t < 31)
            g_zg[k * 32 + bb] = lemb[(size_t)lab[bb * 32 + t] * 256 + k];
    }
}

// ---------------- inp = h_lstm·Winᵀ + bin ----------------
__global__ void k_inp(const float* __restrict__ Win, const float* __restrict__ bin) {
    int lane = threadIdx.x & 31, w = threadIdx.x >> 5;
    int r0 = (blockIdx.x * 8 + w) * 4;
    float acc[4] = {0, 0, 0, 0};
    acc4<512, 512>(Win, r0, g_zinp, lane, acc);
#pragma unroll
    for (int i = 0; i < 4; i++)
        g_inp[lane * 512 + r0 + i] = acc[i] + bin[r0 + i];
}

// ---------------- fused attention: scores + online softmax + weighted partials ----------------
__global__ void k_attn(const float* __restrict__ Vv) {
    int cix = blockIdx.x, b = blockIdx.y;
    int tid = threadIdx.x, lane = tid & 31, wid = tid >> 5;
    float4 v4[4], i4[4];
#pragma unroll
    for (int q = 0; q < 4; q++) {
        v4[q] = *(const float4*)(Vv + (q * 32 + lane) * 4);
        i4[q] = *(const float4*)(g_inp + b * 512 + (q * 32 + lane) * 4);
    }
    float wacc[16];
#pragma unroll
    for (int j = 0; j < 16; j++) wacc[j] = 0.0f;
    float m = -1e30f, d = 0.0f;
    const float* cb = g_ctx + ((size_t)b * 2048 + cix * 128) * 512;
    for (int s = wid; s < 128; s += 8) {
        const float* row = cb + s * 512;
        float4 c4[4];
        float p = 0.0f;
#pragma unroll
        for (int q = 0; q < 4; q++) {
            c4[q] = *(const float4*)(row + (q * 32 + lane) * 4);
            p = fmaf(v4[q].x, tanh_ffma(i4[q].x + c4[q].x), p);
            p = fmaf(v4[q].y, tanh_ffma(i4[q].y + c4[q].y), p);
            p = fmaf(v4[q].z, tanh_ffma(i4[q].z + c4[q].z), p);
            p = fmaf(v4[q].w, tanh_ffma(i4[q].w + c4[q].w), p);
        }
#pragma unroll
        for (int o = 16; o; o >>= 1) p += __shfl_xor_sync(0xffffffffu, p, o);
        float mn = fmaxf(m, p);
        float sc = ex2f((m - mn) * L2E);
        float pe = ex2f((p - mn) * L2E);
        d = fmaf(d, sc, pe);
#pragma unroll
        for (int q = 0; q < 4; q++) {
            wacc[q * 4 + 0] = fmaf(wacc[q * 4 + 0], sc, pe * c4[q].x);
            wacc[q * 4 + 1] = fmaf(wacc[q * 4 + 1], sc, pe * c4[q].y);
            wacc[q * 4 + 2] = fmaf(wacc[q * 4 + 2], sc, pe * c4[q].z);
            wacc[q * 4 + 3] = fmaf(wacc[q * 4 + 3], sc, pe * c4[q].w);
        }
        m = mn;
    }
    __shared__ float4 smw[8 * 128];
    __shared__ float smm[8], smd[8];
    if (lane == 0) { smm[wid] = m; smd[wid] = d; }
    __syncthreads();
    float mg = -1e30f;
#pragma unroll
    for (int j = 0; j < 8; j++) mg = fmaxf(mg, smm[j]);
    float sc = ex2f((m - mg) * L2E);
#pragma unroll
    for (int q = 0; q < 4; q++)
        smw[wid * 128 + q * 32 + lane] =
            make_float4(wacc[q * 4 + 0] * sc, wacc[q * 4 + 1] * sc,
                        wacc[q * 4 + 2] * sc, wacc[q * 4 + 3] * sc);
    float dg = 0.0f;
#pragma unroll
    for (int j = 0; j < 8; j++) dg = fmaf(smd[j], ex2f((smm[j] - mg) * L2E), dg);
    __syncthreads();
    if (tid < 128) {
        float4 a = make_float4(0, 0, 0, 0);
#pragma unroll
        for (int w2 = 0; w2 < 8; w2++) {
            float4 v = smw[w2 * 128 + tid];
            a.x += v.x; a.y += v.y; a.z += v.z; a.w += v.w;
        }
        *(float4*)(g_cw + (size_t)(b * 16 + cix) * 512 + tid * 4) = a;
    }
    if (tid == 0) { g_cm[b * 16 + cix] = mg; g_cd[b * 16 + cix] = dg; }
}

// ---------------- combine chunks -> weighted ----------------
__global__ void k_combine() {
    int b = blockIdx.x, h = threadIdx.x;   // 32 x 512
    float m = -1e30f;
#pragma unroll
    for (int c = 0; c < 16; c++) m = fmaxf(m, g_cm[b * 16 + c]);
    float num = 0.0f, den = 0.0f;
#pragma unroll
    for (int c = 0; c < 16; c++) {
        float e = ex2f((g_cm[b * 16 + c] - m) * L2E);
        den = fmaf(e, g_cd[b * 16 + c], den);
        num = fmaf(e, g_cw[(size_t)(b * 16 + c) * 512 + h], num);
    }
    float w = num * rcpf(den);
    g_zho[h * 32 + b] = w;
    g_zlog[(512 + h) * 32 + b] = w;
}

// ---------------- h_t = tanh([weighted,h_lstm]·Whoᵀ + bho) ----------------
__global__ void k_hout(const float* __restrict__ Who, const float* __restrict__ bho) {
    int lane = threadIdx.x & 31, w = threadIdx.x >> 5;
    int r0 = (blockIdx.x * 8 + w) * 4;
    float acc[4] = {0, 0, 0, 0};
    acc4<1024, 1024>(Who, r0, g_zho, lane, acc);
#pragma unroll
    for (int i = 0; i < 4; i++) {
        float th = mufu_tanh(acc[i] + bho[r0 + i]);
        g_zg[(256 + r0 + i) * 32 + lane] = th;   // next-step h
        g_zlog[(r0 + i) * 32 + lane] = th;       // logits operand
    }
}

// ---------------- logits: out = [h_t,weighted,x]·Woutᵀ + bout ----------------
__global__ void k_logits(const float* __restrict__ Wout, const float* __restrict__ bout,
                         float* __restrict__ out, int t) {
    int lane = threadIdx.x & 31, w = threadIdx.x >> 5;
    int r0 = (blockIdx.x * 8 + w) * 4;
    if (r0 >= 2000) return;
    float acc[4] = {0, 0, 0, 0};
    acc4<1280, 1280>(Wout, r0, g_zlog, lane, acc);
#pragma unroll
    for (int i = 0; i < 4; i++)
        out[(size_t)lane * 64000 + t * 2000 + r0 + i] = acc[i] + bout[r0 + i];
}

// ---------------- argmax per (b, t) ----------------
__global__ void k_argmax(float* __restrict__ out, int t) {
    int b = blockIdx.x, tid = threadIdx.x;
    const float* row = out + (size_t)b * 64000 + t * 2000;
    float bv = -1e38f; int bi = 0;
    for (int r = tid; r < 2000; r += 256) {
        float v = row[r];
        if (v > bv) { bv = v; bi = r; }
    }
#pragma unroll
    for (int o = 16; o; o >>= 1) {
        float ov = __shfl_xor_sync(0xffffffffu, bv, o);
        int oi = __shfl_xor_sync(0xffffffffu, bi, o);
        if (ov > bv || (ov == bv && oi < bi)) { bv = ov; bi = oi; }
    }
    __shared__ float sv[8]; __shared__ int si[8];
    if ((tid & 31) == 0) { sv[tid >> 5] = bv; si[tid >> 5] = bi; }
    __syncthreads();
    if (tid == 0) {
        for (int j = 1; j < 8; j++)
            if (sv[j] > bv || (sv[j] == bv && si[j] < bi)) { bv = sv[j]; bi = si[j]; }
        out[2048000 + b * 32 + t] = (float)bi;
    }
}

// ---------------- final h_f, c_f ----------------
__global__ void k_final(float* __restrict__ out) {
    int b = blockIdx.x, h = threadIdx.x;   // 32 x 512
    out[2049024 + b * 512 + h] = g_zg[(256 + h) * 32 + b];
    out[2065408 + b * 512 + h] = g_cbuf[0][h * 32 + b];   // t=31 wrote cbuf[(31+1)&1]=0
}

extern "C" void kernel_launch(void* const* d_in, const int* in_sizes, int n_in,
                              void* d_out, int out_size) {
    int off = (n_in >= 21) ? 0 : -1;   // output_length scalar may or may not be passed
    const float* dec  = (const float*)d_in[2 + off];
    const float* h0   = (const float*)d_in[3 + off];
    const float* c0   = (const float*)d_in[4 + off];
    const float* ctxi = (const float*)d_in[5 + off];
    const int*   lab  = (const int*)  d_in[6 + off];
    const float* lemb = (const float*)d_in[7 + off];
    const float* Wih  = (const float*)d_in[8 + off];
    const float* bih  = (const float*)d_in[9 + off];
    const float* Whh  = (const float*)d_in[10 + off];
    const float* bhh  = (const float*)d_in[11 + off];
    const float* Win  = (const float*)d_in[12 + off];
    const float* bin  = (const float*)d_in[13 + off];
    const float* Wctx = (const float*)d_in[14 + off];
    const float* bctx = (const float*)d_in[15 + off];
    const float* V    = (const float*)d_in[16 + off];
    const float* Who  = (const float*)d_in[17 + off];
    const float* bho  = (const float*)d_in[18 + off];
    const float* Wout = (const float*)d_in[19 + off];
    const float* bout = (const float*)d_in[20 + off];
    float* out = (float*)d_out;

    k_ctx_gemm<<<dim3(512, 4), 256>>>(ctxi, Wctx, bctx);
    k_pre<<<64, 256>>>(dec, h0);
    for (int t = 0; t < 32; t++) {
        k_gates<<<64, 256>>>(Wih, bih, Whh, bhh);
        k_point<<<64, 256>>>(c0, dec, lab, lemb, t);
        k_inp<<<16, 256>>>(Win, bin);
        k_attn<<<dim3(16, 32), 256>>>(V);
        k_combine<<<32, 512>>>();
        k_hout<<<16, 256>>>(Who, bho);
        k_logits<<<63, 256>>>(Wout, bout, out, t);
        k_argmax<<<32, 256>>>(out, t);
    }
    k_final<<<32, 512>>>(out);
}

// round 4
// speedup vs baseline: 1.3826x; 1.3826x over previous
#include <cuda_runtime.h>
#include <cstdint>

#define Bz 32
#define Sz 2048
#define Hz 512
#define Ez 256
#define NLz 2000
#define Tz 32
#define NCH 16
#define CHS 128
#define L2E 1.4426950408889634f

// ---------------- device scratch ----------------
__device__ float g_ctx[(size_t)Bz * Sz * Hz];      // [b*S+s][h]  128 MB
__device__ float g_zg[768 * Bz];                   // gates operand: rows 0..255 x, 256..767 h
__device__ float g_zinp[Hz * Bz];                  // h_lstm, operand for inp
__device__ float g_zho[1024 * Bz];                 // 0..511 weighted, 512..1023 h_lstm
__device__ float g_zlog[1280 * Bz];                // 0..511 h_t, 512..1023 weighted, 1024..1279 x
__device__ float g_gates[4 * Hz * Bz];             // [r][b]
__device__ float g_cbuf[2][Hz * Bz];               // [h][b]
__device__ float g_inp[Bz * Hz];                   // [b][h]
__device__ float g_cw[Bz * NCH * Hz];
__device__ float g_cm[Bz * NCH];
__device__ float g_cd[Bz * NCH];

// ---------------- math ----------------
__device__ __forceinline__ float ex2f(float x) {
    float y; asm("ex2.approx.f32 %0, %1;" : "=f"(y) : "f"(x)); return y;
}
__device__ __forceinline__ float rcpf(float x) {
    float y; asm("rcp.approx.f32 %0, %1;" : "=f"(y) : "f"(x)); return y;
}
__device__ __forceinline__ float mufu_tanh(float x) {
    float e = ex2f(x * (2.0f * L2E));
    return fmaf(-2.0f, rcpf(e + 1.0f), 1.0f);
}
__device__ __forceinline__ float mufu_sigmoid(float x) {
    return rcpf(1.0f + ex2f(-x * L2E));
}

// ---------------- warp-row GEMM helper: 2 rows, lane=batch ----------------
template <int K, int LD>
__device__ __forceinline__ void acc2(const float* __restrict__ W, int r0,
                                     const float* __restrict__ z, int lane,
                                     float acc[2]) {
#pragma unroll 4
    for (int k = 0; k < K; k += 4) {
        float z0 = z[(k + 0) * 32 + lane];
        float z1 = z[(k + 1) * 32 + lane];
        float z2 = z[(k + 2) * 32 + lane];
        float z3 = z[(k + 3) * 32 + lane];
#pragma unroll
        for (int i = 0; i < 2; i++) {
            float4 wv = *(const float4*)(W + (size_t)(r0 + i) * LD + k);
            acc[i] = fmaf(wv.x, z0, acc[i]);
            acc[i] = fmaf(wv.y, z1, acc[i]);
            acc[i] = fmaf(wv.z, z2, acc[i]);
            acc[i] = fmaf(wv.w, z3, acc[i]);
        }
    }
}

// ---------------- ctx GEMM (one-time): g_ctx[m][n] = context[m][:]·Wctx[n][:] + bctx[n] ----------------
__global__ void k_ctx_gemm(const float* __restrict__ A, const float* __restrict__ W,
                           const float* __restrict__ bias) {
    __shared__ float As[8][128];
    __shared__ float Ws[8][128];
    int tid = threadIdx.x;
    int bm = blockIdx.x * 128, bn = blockIdx.y * 128;
    int lr = tid >> 1, lk = (tid & 1) * 4;
    int tm = (tid >> 4) * 8, tn = (tid & 15) * 8;
    float acc[8][8];
#pragma unroll
    for (int i = 0; i < 8; i++)
#pragma unroll
        for (int j = 0; j < 8; j++) acc[i][j] = 0.0f;
    const float* Ap = A + (size_t)(bm + lr) * 512 + lk;
    const float* Wp = W + (size_t)(bn + lr) * 512 + lk;
    for (int k0 = 0; k0 < 512; k0 += 8) {
        float4 a4 = *(const float4*)(Ap + k0);
        float4 w4 = *(const float4*)(Wp + k0);
        As[lk + 0][lr] = a4.x; As[lk + 1][lr] = a4.y;
        As[lk + 2][lr] = a4.z; As[lk + 3][lr] = a4.w;
        Ws[lk + 0][lr] = w4.x; Ws[lk + 1][lr] = w4.y;
        Ws[lk + 2][lr] = w4.z; Ws[lk + 3][lr] = w4.w;
        __syncthreads();
#pragma unroll
        for (int kk = 0; kk < 8; kk++) {
            float4 a0 = *(const float4*)&As[kk][tm];
            float4 a1 = *(const float4*)&As[kk][tm + 4];
            float4 w0 = *(const float4*)&Ws[kk][tn];
            float4 w1 = *(const float4*)&Ws[kk][tn + 4];
            float ar[8] = {a0.x, a0.y, a0.z, a0.w, a1.x, a1.y, a1.z, a1.w};
            float wr[8] = {w0.x, w0.y, w0.z, w0.w, w1.x, w1.y, w1.z, w1.w};
#pragma unroll
            for (int i = 0; i < 8; i++)
#pragma unroll
                for (int j = 0; j < 8; j++) acc[i][j] = fmaf(ar[i], wr[j], acc[i][j]);
        }
        __syncthreads();
    }
#pragma unroll
    for (int i = 0; i < 8; i++) {
        float* o = g_ctx + (size_t)(bm + tm + i) * 512 + bn + tn;
#pragma unroll
        for (int j = 0; j < 8; j++) o[j] = acc[i][j] + bias[bn + tn + j];
    }
}

// ---------------- pre: stage x(0) and h0 into g_zg ----------------
__global__ void k_pre(const float* __restrict__ dec, const float* __restrict__ h0) {
    int idx = blockIdx.x * 256 + threadIdx.x;      // 64*256 = 16384
    int b = idx & 31, h = idx >> 5;
    g_zg[(256 + h) * 32 + b] = h0[b * 512 + h];
    if (idx < 8192) {
        int bb = idx >> 8, k = idx & 255;
        g_zg[k * 32 + bb] = dec[bb * 256 + k];
    }
}

// ---------------- gates: 2048 rows, 2 rows/warp -> 128 blocks ----------------
__global__ __launch_bounds__(256) void k_gates(const float* __restrict__ Wih,
                                               const float* __restrict__ bih,
                                               const float* __restrict__ Whh,
                                               const float* __restrict__ bhh) {
    int lane = threadIdx.x & 31, w = threadIdx.x >> 5;
    int r0 = (blockIdx.x * 8 + w) * 2;
    float acc[2] = {0, 0};
    acc2<256, 256>(Wih, r0, g_zg, lane, acc);
    acc2<512, 512>(Whh, r0, g_zg + 256 * 32, lane, acc);
#pragma unroll
    for (int i = 0; i < 2; i++)
        g_gates[(r0 + i) * 32 + lane] = acc[i] + bih[r0 + i] + bhh[r0 + i];
}

// ---------------- LSTM pointwise + staging ----------------
__global__ void k_point(const float* __restrict__ c0, const float* __restrict__ dec,
                        const int* __restrict__ lab, const float* __restrict__ lemb, int t) {
    int idx = blockIdx.x * 256 + threadIdx.x;      // 16384
    int b = idx & 31, h = idx >> 5;
    const float* cin = g_cbuf[t & 1];
    float* cout = g_cbuf[(t + 1) & 1];
    float gi = mufu_sigmoid(g_gates[h * 32 + b]);
    float gf = mufu_sigmoid(g_gates[(512 + h) * 32 + b]);
    float gg = mufu_tanh(g_gates[(1024 + h) * 32 + b]);
    float go = mufu_sigmoid(g_gates[(1536 + h) * 32 + b]);
    float c_old = (t == 0) ? c0[b * 512 + h] : cin[h * 32 + b];
    float ct = fmaf(gf, c_old, gi * gg);
    float hl = go * mufu_tanh(ct);
    cout[h * 32 + b] = ct;
    g_zinp[h * 32 + b] = hl;
    g_zho[(512 + h) * 32 + b] = hl;
    if (idx < 8192) {
        int bb = idx >> 8, k = idx & 255;
        float xv = (t == 0) ? dec[bb * 256 + k]
                            : lemb[(size_t)lab[bb * 32 + (t - 1)] * 256 + k];
        g_zlog[(1024 + k) * 32 + bb] = xv;
        if (t < 31)
            g_zg[k * 32 + bb] = lemb[(size_t)lab[bb * 32 + t] * 256 + k];
    }
}

// ---------------- inp = h_lstm·Winᵀ + bin : 512 rows -> 32 blocks ----------------
__global__ __launch_bounds__(256) void k_inp(const float* __restrict__ Win,
                                             const float* __restrict__ bin) {
    int lane = threadIdx.x & 31, w = threadIdx.x >> 5;
    int r0 = (blockIdx.x * 8 + w) * 2;
    float acc[2] = {0, 0};
    acc2<512, 512>(Win, r0, g_zinp, lane, acc);
#pragma unroll
    for (int i = 0; i < 2; i++)
        g_inp[lane * 512 + r0 + i] = acc[i] + bin[r0 + i];
}

// ---------------- fused attention: MUFU tanh, online softmax, single ctx pass ----------------
// V·tanh(x) = V - 2V·rcp(ex2(2·log2e·x) + 1)
__global__ __launch_bounds__(256) void k_attn(const float* __restrict__ Vv) {
    int cix = blockIdx.x, b = blockIdx.y;
    int tid = threadIdx.x, lane = tid & 31, wid = tid >> 5;
    float4 tv[4];   // 2*V
    float4 is[4];   // inp scaled by 2*log2e
    float sumV = 0.0f;
#pragma unroll
    for (int q = 0; q < 4; q++) {
        float4 v = *(const float4*)(Vv + (q * 32 + lane) * 4);
        sumV += v.x + v.y + v.z + v.w;
        tv[q] = make_float4(2.0f * v.x, 2.0f * v.y, 2.0f * v.z, 2.0f * v.w);
        float4 ii = *(const float4*)(g_inp + b * 512 + (q * 32 + lane) * 4);
        const float c = 2.0f * L2E;
        is[q] = make_float4(ii.x * c, ii.y * c, ii.z * c, ii.w * c);
    }
    float wacc[16];
#pragma unroll
    for (int j = 0; j < 16; j++) wacc[j] = 0.0f;
    float m = -1e30f, d = 0.0f;
    const float* cb = g_ctx + ((size_t)b * 2048 + cix * 128) * 512;

    for (int s = wid; s < 128; s += 8) {
        const float* row = cb + s * 512;
        float4 c4[4];
        float pn = 0.0f;   // sum 2V*r  (score = sumV - pn, before reduce)
#pragma unroll
        for (int q = 0; q < 4; q++) {
            c4[q] = *(const float4*)(row + (q * 32 + lane) * 4);
            const float c = 2.0f * L2E;
            float e0 = ex2f(fmaf(c4[q].x, c, is[q].x));
            float e1 = ex2f(fmaf(c4[q].y, c, is[q].y));
            float e2 = ex2f(fmaf(c4[q].z, c, is[q].z));
            float e3 = ex2f(fmaf(c4[q].w, c, is[q].w));
            pn = fmaf(tv[q].x, rcpf(e0 + 1.0f), pn);
            pn = fmaf(tv[q].y, rcpf(e1 + 1.0f), pn);
            pn = fmaf(tv[q].z, rcpf(e2 + 1.0f), pn);
            pn = fmaf(tv[q].w, rcpf(e3 + 1.0f), pn);
        }
        float p = sumV - pn;
#pragma unroll
        for (int o = 16; o; o >>= 1) p += __shfl_xor_sync(0xffffffffu, p, o);
        float mn = fmaxf(m, p);
        float sc = ex2f((m - mn) * L2E);
        float pe = ex2f((p - mn) * L2E);
        d = fmaf(d, sc, pe);
#pragma unroll
        for (int q = 0; q < 4; q++) {
            wacc[q * 4 + 0] = fmaf(wacc[q * 4 + 0], sc, pe * c4[q].x);
            wacc[q * 4 + 1] = fmaf(wacc[q * 4 + 1], sc, pe * c4[q].y);
            wacc[q * 4 + 2] = fmaf(wacc[q * 4 + 2], sc, pe * c4[q].z);
            wacc[q * 4 + 3] = fmaf(wacc[q * 4 + 3], sc, pe * c4[q].w);
        }
        m = mn;
    }
    __shared__ float4 smw[8 * 128];
    __shared__ float smm[8], smd[8];
    if (lane == 0) { smm[wid] = m; smd[wid] = d; }
    __syncthreads();
    float mg = -1e30f;
#pragma unroll
    for (int j = 0; j < 8; j++) mg = fmaxf(mg, smm[j]);
    float sc = ex2f((m - mg) * L2E);
#pragma unroll
    for (int q = 0; q < 4; q++)
        smw[wid * 128 + q * 32 + lane] =
            make_float4(wacc[q * 4 + 0] * sc, wacc[q * 4 + 1] * sc,
                        wacc[q * 4 + 2] * sc, wacc[q * 4 + 3] * sc);
    float dg = 0.0f;
#pragma unroll
    for (int j = 0; j < 8; j++) dg = fmaf(smd[j], ex2f((smm[j] - mg) * L2E), dg);
    __syncthreads();
    if (tid < 128) {
        float4 a = make_float4(0, 0, 0, 0);
#pragma unroll
        for (int w2 = 0; w2 < 8; w2++) {
            float4 v = smw[w2 * 128 + tid];
            a.x += v.x; a.y += v.y; a.z += v.z; a.w += v.w;
        }
        *(float4*)(g_cw + (size_t)(b * 16 + cix) * 512 + tid * 4) = a;
    }
    if (tid == 0) { g_cm[b * 16 + cix] = mg; g_cd[b * 16 + cix] = dg; }
}

// ---------------- combine chunks -> weighted ----------------
__global__ void k_combine() {
    int b = blockIdx.x, h = threadIdx.x;   // 32 x 512
    float m = -1e30f;
#pragma unroll
    for (int c = 0; c < 16; c++) m = fmaxf(m, g_cm[b * 16 + c]);
    float num = 0.0f, den = 0.0f;
#pragma unroll
    for (int c = 0; c < 16; c++) {
        float e = ex2f((g_cm[b * 16 + c] - m) * L2E);
        den = fmaf(e, g_cd[b * 16 + c], den);
        num = fmaf(e, g_cw[(size_t)(b * 16 + c) * 512 + h], num);
    }
    float w = num * rcpf(den);
    g_zho[h * 32 + b] = w;
    g_zlog[(512 + h) * 32 + b] = w;
}

// ---------------- h_t = tanh([weighted,h_lstm]·Whoᵀ + bho) : 32 blocks ----------------
__global__ __launch_bounds__(256) void k_hout(const float* __restrict__ Who,
                                              const float* __restrict__ bho) {
    int lane = threadIdx.x & 31, w = threadIdx.x >> 5;
    int r0 = (blockIdx.x * 8 + w) * 2;
    float acc[2] = {0, 0};
    acc2<1024, 1024>(Who, r0, g_zho, lane, acc);
#pragma unroll
    for (int i = 0; i < 2; i++) {
        float th = mufu_tanh(acc[i] + bho[r0 + i]);
        g_zg[(256 + r0 + i) * 32 + lane] = th;   // next-step h
        g_zlog[(r0 + i) * 32 + lane] = th;       // logits operand
    }
}

// ---------------- logits: 2000 rows, 2 rows/warp -> 125 blocks ----------------
__global__ __launch_bounds__(256) void k_logits(const float* __restrict__ Wout,
                                                const float* __restrict__ bout,
                                                float* __restrict__ out, int t) {
    int lane = threadIdx.x & 31, w = threadIdx.x >> 5;
    int r0 = (blockIdx.x * 8 + w) * 2;
    if (r0 >= 2000) return;
    float acc[2] = {0, 0};
    acc2<1280, 1280>(Wout, r0, g_zlog, lane, acc);
#pragma unroll
    for (int i = 0; i < 2; i++)
        out[(size_t)lane * 64000 + t * 2000 + r0 + i] = acc[i] + bout[r0 + i];
}

// ---------------- argmax per (b, t) ----------------
__global__ void k_argmax(float* __restrict__ out, int t) {
    int b = blockIdx.x, tid = threadIdx.x;
    const float* row = out + (size_t)b * 64000 + t * 2000;
    float bv = -1e38f; int bi = 0;
    for (int r = tid; r < 2000; r += 256) {
        float v = row[r];
        if (v > bv) { bv = v; bi = r; }
    }
#pragma unroll
    for (int o = 16; o; o >>= 1) {
        float ov = __shfl_xor_sync(0xffffffffu, bv, o);
        int oi = __shfl_xor_sync(0xffffffffu, bi, o);
        if (ov > bv || (ov == bv && oi < bi)) { bv = ov; bi = oi; }
    }
    __shared__ float sv[8]; __shared__ int si[8];
    if ((tid & 31) == 0) { sv[tid >> 5] = bv; si[tid >> 5] = bi; }
    __syncthreads();
    if (tid == 0) {
        for (int j = 1; j < 8; j++)
            if (sv[j] > bv || (sv[j] == bv && si[j] < bi)) { bv = sv[j]; bi = si[j]; }
        out[2048000 + b * 32 + t] = (float)bi;
    }
}

// ---------------- final h_f, c_f ----------------
__global__ void k_final(float* __restrict__ out) {
    int b = blockIdx.x, h = threadIdx.x;   // 32 x 512
    out[2049024 + b * 512 + h] = g_zg[(256 + h) * 32 + b];
    out[2065408 + b * 512 + h] = g_cbuf[0][h * 32 + b];   // t=31 wrote cbuf[0]
}

extern "C" void kernel_launch(void* const* d_in, const int* in_sizes, int n_in,
                              void* d_out, int out_size) {
    int off = (n_in >= 21) ? 0 : -1;
    const float* dec  = (const float*)d_in[2 + off];
    const float* h0   = (const float*)d_in[3 + off];
    const float* c0   = (const float*)d_in[4 + off];
    const float* ctxi = (const float*)d_in[5 + off];
    const int*   lab  = (const int*)  d_in[6 + off];
    const float* lemb = (const float*)d_in[7 + off];
    const float* Wih  = (const float*)d_in[8 + off];
    const float* bih  = (const float*)d_in[9 + off];
    const float* Whh  = (const float*)d_in[10 + off];
    const float* bhh  = (const float*)d_in[11 + off];
    const float* Win  = (const float*)d_in[12 + off];
    const float* bin  = (const float*)d_in[13 + off];
    const float* Wctx = (const float*)d_in[14 + off];
    const float* bctx = (const float*)d_in[15 + off];
    const float* V    = (const float*)d_in[16 + off];
    const float* Who  = (const float*)d_in[17 + off];
    const float* bho  = (const float*)d_in[18 + off];
    const float* Wout = (const float*)d_in[19 + off];
    const float* bout = (const float*)d_in[20 + off];
    float* out = (float*)d_out;

    k_ctx_gemm<<<dim3(512, 4), 256>>>(ctxi, Wctx, bctx);
    k_pre<<<64, 256>>>(dec, h0);
    for (int t = 0; t < 32; t++) {
        k_gates<<<128, 256>>>(Wih, bih, Whh, bhh);
        k_point<<<64, 256>>>(c0, dec, lab, lemb, t);
        k_inp<<<32, 256>>>(Win, bin);
        k_attn<<<dim3(16, 32), 256>>>(V);
        k_combine<<<32, 512>>>();
        k_hout<<<32, 256>>>(Who, bho);
        k_logits<<<125, 256>>>(Wout, bout, out, t);
        k_argmax<<<32, 256>>>(out, t);
    }
    k_final<<<32, 512>>>(out);
}